// round 13
// baseline (speedup 1.0000x reference)
#include <cuda_runtime.h>
#include <cstdint>

// Problem constants
#define T_SEQ  2048
#define C_DIM  1024
#define NHEAD  16
#define HDIM   64
#define BATCH  4
#define M_TOT  (BATCH * T_SEQ)   // 8192
#define K_DIM  1024

// Scratch (allocation-free rule: __device__ globals)
__device__ float g_q[BATCH * NHEAD * T_SEQ * HDIM];  // [BH, T, D]
__device__ float g_k[BATCH * NHEAD * T_SEQ * HDIM];
__device__ float g_v[BATCH * NHEAD * T_SEQ * HDIM];
__device__ float g_y[M_TOT * C_DIM];                 // [B*T, C]

// ---------------- packed f32x2 helpers (FFMA2 — PTX-only on sm_103a) ----------
__device__ __forceinline__ unsigned long long pack2(float lo, float hi) {
    unsigned long long r;
    asm("mov.b64 %0, {%1, %2};" : "=l"(r) : "f"(lo), "f"(hi));
    return r;
}
__device__ __forceinline__ void fma2(unsigned long long& d,
                                     unsigned long long a,
                                     unsigned long long b) {
    asm("fma.rn.f32x2 %0, %1, %2, %3;" : "=l"(d) : "l"(a), "l"(b), "l"(d));
}
__device__ __forceinline__ float2 unpack2(unsigned long long v) {
    float lo, hi;
    asm("mov.b64 {%0, %1}, %2;" : "=f"(lo), "=f"(hi) : "l"(v));
    return make_float2(lo, hi);
}

// ---------------- GEMM: out[m,n] = sum_k A[m,k] * W[n,k] + bias[n] ------------
// MODE 0: A = x (param); blockIdx.z selects (Wq,bq)->g_q, (Wk,bk)->g_k, (Wv,bv)->g_v
//         epilogue scatters to [B,H,T,D]
// MODE 1: A = g_y; W0/b0 = Wp/bp; plain row-major write to out0
template <int MODE>
__global__ __launch_bounds__(256, 2)
void gemm_kernel(const float* __restrict__ A,
                 const float* __restrict__ W0, const float* __restrict__ W1,
                 const float* __restrict__ W2,
                 const float* __restrict__ b0, const float* __restrict__ b1,
                 const float* __restrict__ b2,
                 float* __restrict__ out0)
{
    __shared__ __align__(16) float As[8 * 132];
    __shared__ __align__(16) float Bs[8 * 132];

    const int n0 = blockIdx.x * 128;
    const int m0 = blockIdx.y * 128;
    const int z  = (MODE == 0) ? (int)blockIdx.z : 0;

    const float* Ap   = (MODE == 0) ? A : (const float*)g_y;
    const float* W    = (MODE == 0) ? (z == 0 ? W0 : (z == 1 ? W1 : W2)) : W0;
    const float* bias = (MODE == 0) ? (z == 0 ? b0 : (z == 1 ? b1 : b2)) : b0;

    const int tid = threadIdx.x;
    const int tx  = tid & 15;
    const int ty  = tid >> 4;
    const int lm  = tid >> 1;          // 0..127 tile row for loads
    const int lk  = (tid & 1) * 4;     // 0 or 4

    const float* aptr = Ap + (size_t)(m0 + lm) * K_DIM + lk;
    const float* wptr = W  + (size_t)(n0 + lm) * K_DIM + lk;

    unsigned long long acc[8][4];
#pragma unroll
    for (int i = 0; i < 8; i++)
#pragma unroll
        for (int p = 0; p < 4; p++) acc[i][p] = 0ull;

    float4 areg = *(const float4*)aptr;
    float4 breg = *(const float4*)wptr;

    for (int kt = 0; kt < K_DIM / 8; ++kt) {
        As[(lk + 0) * 132 + lm] = areg.x;
        As[(lk + 1) * 132 + lm] = areg.y;
        As[(lk + 2) * 132 + lm] = areg.z;
        As[(lk + 3) * 132 + lm] = areg.w;
        Bs[(lk + 0) * 132 + lm] = breg.x;
        Bs[(lk + 1) * 132 + lm] = breg.y;
        Bs[(lk + 2) * 132 + lm] = breg.z;
        Bs[(lk + 3) * 132 + lm] = breg.w;
        __syncthreads();
        if (kt + 1 < K_DIM / 8) {
            areg = *(const float4*)(aptr + (kt + 1) * 8);
            breg = *(const float4*)(wptr + (kt + 1) * 8);
        }
#pragma unroll
        for (int k = 0; k < 8; ++k) {
            float4 a0 = *(const float4*)&As[k * 132 + ty * 4];
            float4 a1 = *(const float4*)&As[k * 132 + 64 + ty * 4];
            ulonglong2 bb0 = *(const ulonglong2*)&Bs[k * 132 + tx * 4];
            ulonglong2 bb1 = *(const ulonglong2*)&Bs[k * 132 + 64 + tx * 4];
            float av[8] = {a0.x, a0.y, a0.z, a0.w, a1.x, a1.y, a1.z, a1.w};
#pragma unroll
            for (int i = 0; i < 8; i++) {
                unsigned long long a2 = pack2(av[i], av[i]);
                fma2(acc[i][0], a2, bb0.x);
                fma2(acc[i][1], a2, bb0.y);
                fma2(acc[i][2], a2, bb1.x);
                fma2(acc[i][3], a2, bb1.y);
            }
        }
        __syncthreads();
    }

    float* dst = (MODE == 0) ? (z == 0 ? g_q : (z == 1 ? g_k : g_v)) : out0;

#pragma unroll
    for (int i = 0; i < 8; i++) {
        const int r = m0 + ((i < 4) ? (ty * 4 + i) : (64 + ty * 4 + (i - 4)));
#pragma unroll
        for (int p = 0; p < 4; p++) {
            const int c = n0 + ((p < 2) ? (tx * 4 + 2 * p)
                                        : (64 + tx * 4 + 2 * (p - 2)));
            float2 v = unpack2(acc[i][p]);
            const float v0 = v.x + bias[c];
            const float v1 = v.y + bias[c + 1];
            if (MODE == 0) {
                const int b = r >> 11;           // / T_SEQ
                const int t = r & (T_SEQ - 1);
                const int h = c >> 6;            // / HDIM
                const int d = c & 63;            // c even -> d,d+1 same head
                float* o = dst + (((size_t)(b * NHEAD + h) * T_SEQ + t) * HDIM);
                o[d]     = v0;
                o[d + 1] = v1;
            } else {
                dst[(size_t)r * C_DIM + c]     = v0;
                dst[(size_t)r * C_DIM + c + 1] = v1;
            }
        }
    }
}

// ---------------- Flash attention (causal, online softmax) -------------------
// grid: (32 query tiles, 64 bh); block: 256 threads
// thread (tx = t&15, ty = t>>4) owns rows r0..r0+3 (r0 = 4*ty) and cols
// c = tx + 16*jj (jj 0..3)  -> conflict-free smem with 65-float row pad.
__global__ __launch_bounds__(256, 2)
void attn_kernel()
{
    extern __shared__ float sm[];
    float* Qs = sm;                 // 64 x 65
    float* Ks = sm + 64 * 65;
    float* Vs = sm + 2 * 64 * 65;
    float* Ps = sm + 3 * 64 * 65;

    const int qtile = (int)gridDim.x - 1 - (int)blockIdx.x;  // heavy blocks first
    const int bh    = blockIdx.y;
    const int tid   = threadIdx.x;
    const int tx    = tid & 15;
    const int ty    = tid >> 4;
    const int r0    = ty * 4;

    const float* qbase = g_q + ((size_t)bh * T_SEQ + qtile * 64) * HDIM;
#pragma unroll
    for (int i = 0; i < 16; ++i) {
        int idx = tid + i * 256;           // 0..4095
        int r = idx >> 6, d = idx & 63;
        Qs[r * 65 + d] = qbase[idx];
    }

    float m[4], l[4], o[4][4];
#pragma unroll
    for (int i = 0; i < 4; ++i) {
        m[i] = -1e30f;
        l[i] = 0.0f;
#pragma unroll
        for (int jj = 0; jj < 4; ++jj) o[i][jj] = 0.0f;
    }
    const float scale = 0.125f;  // 1/sqrt(64)

    for (int j = 0; j <= qtile; ++j) {
        const float* kb = g_k + ((size_t)bh * T_SEQ + j * 64) * HDIM;
        const float* vb = g_v + ((size_t)bh * T_SEQ + j * 64) * HDIM;
        __syncthreads();   // previous tile fully consumed
#pragma unroll
        for (int i = 0; i < 16; ++i) {
            int idx = tid + i * 256;
            int r = idx >> 6, d = idx & 63;
            Ks[r * 65 + d] = kb[idx];
            Vs[r * 65 + d] = vb[idx];
        }
        __syncthreads();

        // S = Q K^T
        float s[4][4];
#pragma unroll
        for (int i = 0; i < 4; ++i)
#pragma unroll
            for (int jj = 0; jj < 4; ++jj) s[i][jj] = 0.0f;

#pragma unroll 8
        for (int d = 0; d < 64; ++d) {
            float qv[4], kv[4];
#pragma unroll
            for (int i = 0; i < 4; ++i)  qv[i]  = Qs[(r0 + i) * 65 + d];
#pragma unroll
            for (int jj = 0; jj < 4; ++jj) kv[jj] = Ks[(tx + 16 * jj) * 65 + d];
#pragma unroll
            for (int i = 0; i < 4; ++i)
#pragma unroll
                for (int jj = 0; jj < 4; ++jj)
                    s[i][jj] = fmaf(qv[i], kv[jj], s[i][jj]);
        }

        const bool diag = (j == qtile);
#pragma unroll
        for (int i = 0; i < 4; ++i)
#pragma unroll
            for (int jj = 0; jj < 4; ++jj) {
                s[i][jj] *= scale;
                if (diag && (tx + 16 * jj) > (r0 + i)) s[i][jj] = -1e30f;
            }

        // row max across the 16 tx-threads
        float mnew[4], alpha[4], ls[4];
#pragma unroll
        for (int i = 0; i < 4; ++i) {
            float v = fmaxf(fmaxf(s[i][0], s[i][1]), fmaxf(s[i][2], s[i][3]));
#pragma unroll
            for (int off = 1; off < 16; off <<= 1)
                v = fmaxf(v, __shfl_xor_sync(0xffffffffu, v, off));
            mnew[i]  = fmaxf(m[i], v);
            alpha[i] = __expf(m[i] - mnew[i]);
        }
#pragma unroll
        for (int i = 0; i < 4; ++i) {
            ls[i] = 0.0f;
#pragma unroll
            for (int jj = 0; jj < 4; ++jj) {
                float p = __expf(s[i][jj] - mnew[i]);
                Ps[(r0 + i) * 65 + tx + 16 * jj] = p;
                ls[i] += p;
            }
        }
#pragma unroll
        for (int i = 0; i < 4; ++i) {
            float v = ls[i];
#pragma unroll
            for (int off = 1; off < 16; off <<= 1)
                v += __shfl_xor_sync(0xffffffffu, v, off);
            l[i] = l[i] * alpha[i] + v;
            m[i] = mnew[i];
#pragma unroll
            for (int jj = 0; jj < 4; ++jj) o[i][jj] *= alpha[i];
        }
        __syncthreads();   // Ps ready

        // O += P V
#pragma unroll 8
        for (int c = 0; c < 64; ++c) {
            float pv[4], vv[4];
#pragma unroll
            for (int i = 0; i < 4; ++i)  pv[i]  = Ps[(r0 + i) * 65 + c];
#pragma unroll
            for (int jj = 0; jj < 4; ++jj) vv[jj] = Vs[c * 65 + tx + 16 * jj];
#pragma unroll
            for (int i = 0; i < 4; ++i)
#pragma unroll
                for (int jj = 0; jj < 4; ++jj)
                    o[i][jj] = fmaf(pv[i], vv[jj], o[i][jj]);
        }
    }

    // epilogue: Y[b, t, h*64 + c] = O / l
    const int b = bh >> 4;
    const int h = bh & 15;
#pragma unroll
    for (int i = 0; i < 4; ++i) {
        const float inv = 1.0f / l[i];
        const int qrow = qtile * 64 + r0 + i;
        float* yb = g_y + ((size_t)(b * T_SEQ + qrow)) * C_DIM + h * HDIM;
#pragma unroll
        for (int jj = 0; jj < 4; ++jj)
            yb[tx + 16 * jj] = o[i][jj] * inv;
    }
}

// ------------------------------------------------------------------------------
extern "C" void kernel_launch(void* const* d_in, const int* in_sizes, int n_in,
                              void* d_out, int out_size)
{
    const float* x  = (const float*)d_in[0];
    const float* Wq = (const float*)d_in[1];
    const float* bq = (const float*)d_in[2];
    const float* Wk = (const float*)d_in[3];
    const float* bk = (const float*)d_in[4];
    const float* Wv = (const float*)d_in[5];
    const float* bv = (const float*)d_in[6];
    const float* Wp = (const float*)d_in[7];
    const float* bp = (const float*)d_in[8];
    float* out = (float*)d_out;

    dim3 blk(256);

    // QKV projections (fused): grid.z = {q,k,v}
    gemm_kernel<0><<<dim3(C_DIM / 128, M_TOT / 128, 3), blk>>>(
        x, Wq, Wk, Wv, bq, bk, bv, nullptr);

    // causal flash attention
    const int smem = 4 * 64 * 65 * (int)sizeof(float);  // 66560 B
    cudaFuncSetAttribute(attn_kernel,
                         cudaFuncAttributeMaxDynamicSharedMemorySize, smem);
    attn_kernel<<<dim3(T_SEQ / 64, BATCH * NHEAD), blk, smem>>>();

    // output projection
    gemm_kernel<1><<<dim3(C_DIM / 128, M_TOT / 128, 1), blk>>>(
        nullptr, Wp, nullptr, nullptr, bp, nullptr, nullptr, out);
}

// round 14
// speedup vs baseline: 1.0059x; 1.0059x over previous
#include <cuda_runtime.h>
#include <cstdint>

// Problem constants
#define T_SEQ  2048
#define C_DIM  1024
#define NHEAD  16
#define HDIM   64
#define BATCH  4
#define M_TOT  (BATCH * T_SEQ)   // 8192
#define K_DIM  1024

// Scratch (allocation-free rule: __device__ globals)
__device__ float g_q[BATCH * NHEAD * T_SEQ * HDIM];  // [BH, T, D]
__device__ float g_k[BATCH * NHEAD * T_SEQ * HDIM];
__device__ float g_v[BATCH * NHEAD * T_SEQ * HDIM];
__device__ float g_y[M_TOT * C_DIM];                 // [B*T, C]

// ---------------- packed f32x2 helpers (FFMA2 — PTX-only on sm_103a) ----------
__device__ __forceinline__ unsigned long long pack2(float lo, float hi) {
    unsigned long long r;
    asm("mov.b64 %0, {%1, %2};" : "=l"(r) : "f"(lo), "f"(hi));
    return r;
}
__device__ __forceinline__ void fma2(unsigned long long& d,
                                     unsigned long long a,
                                     unsigned long long b) {
    asm("fma.rn.f32x2 %0, %1, %2, %3;" : "=l"(d) : "l"(a), "l"(b), "l"(d));
}
__device__ __forceinline__ float2 unpack2(unsigned long long v) {
    float lo, hi;
    asm("mov.b64 {%0, %1}, %2;" : "=f"(lo), "=f"(hi) : "l"(v));
    return make_float2(lo, hi);
}

// ---------------- GEMM: out[m,n] = sum_k A[m,k] * W[n,k] + bias[n] ------------
// MODE 0: A = x (param); blockIdx.z selects (Wq,bq)->g_q, (Wk,bk)->g_k, (Wv,bv)->g_v
//         epilogue scatters to [B,H,T,D]
// MODE 1: A = g_y; W0/b0 = Wp/bp; plain row-major write to out0
template <int MODE>
__global__ __launch_bounds__(256, 2)
void gemm_kernel(const float* __restrict__ A,
                 const float* __restrict__ W0, const float* __restrict__ W1,
                 const float* __restrict__ W2,
                 const float* __restrict__ b0, const float* __restrict__ b1,
                 const float* __restrict__ b2,
                 float* __restrict__ out0)
{
    __shared__ __align__(16) float As[8 * 132];
    __shared__ __align__(16) float Bs[8 * 132];

    const int n0 = blockIdx.x * 128;
    const int m0 = blockIdx.y * 128;
    const int z  = (MODE == 0) ? (int)blockIdx.z : 0;

    const float* Ap   = (MODE == 0) ? A : (const float*)g_y;
    const float* W    = (MODE == 0) ? (z == 0 ? W0 : (z == 1 ? W1 : W2)) : W0;
    const float* bias = (MODE == 0) ? (z == 0 ? b0 : (z == 1 ? b1 : b2)) : b0;

    const int tid = threadIdx.x;
    const int tx  = tid & 15;
    const int ty  = tid >> 4;
    const int lm  = tid >> 1;          // 0..127 tile row for loads
    const int lk  = (tid & 1) * 4;     // 0 or 4

    const float* aptr = Ap + (size_t)(m0 + lm) * K_DIM + lk;
    const float* wptr = W  + (size_t)(n0 + lm) * K_DIM + lk;

    unsigned long long acc[8][4];
#pragma unroll
    for (int i = 0; i < 8; i++)
#pragma unroll
        for (int p = 0; p < 4; p++) acc[i][p] = 0ull;

    float4 areg = *(const float4*)aptr;
    float4 breg = *(const float4*)wptr;

    for (int kt = 0; kt < K_DIM / 8; ++kt) {
        As[(lk + 0) * 132 + lm] = areg.x;
        As[(lk + 1) * 132 + lm] = areg.y;
        As[(lk + 2) * 132 + lm] = areg.z;
        As[(lk + 3) * 132 + lm] = areg.w;
        Bs[(lk + 0) * 132 + lm] = breg.x;
        Bs[(lk + 1) * 132 + lm] = breg.y;
        Bs[(lk + 2) * 132 + lm] = breg.z;
        Bs[(lk + 3) * 132 + lm] = breg.w;
        __syncthreads();
        if (kt + 1 < K_DIM / 8) {
            areg = *(const float4*)(aptr + (kt + 1) * 8);
            breg = *(const float4*)(wptr + (kt + 1) * 8);
        }
#pragma unroll
        for (int k = 0; k < 8; ++k) {
            float4 a0 = *(const float4*)&As[k * 132 + ty * 4];
            float4 a1 = *(const float4*)&As[k * 132 + 64 + ty * 4];
            ulonglong2 bb0 = *(const ulonglong2*)&Bs[k * 132 + tx * 4];
            ulonglong2 bb1 = *(const ulonglong2*)&Bs[k * 132 + 64 + tx * 4];
            float av[8] = {a0.x, a0.y, a0.z, a0.w, a1.x, a1.y, a1.z, a1.w};
#pragma unroll
            for (int i = 0; i < 8; i++) {
                unsigned long long a2 = pack2(av[i], av[i]);
                fma2(acc[i][0], a2, bb0.x);
                fma2(acc[i][1], a2, bb0.y);
                fma2(acc[i][2], a2, bb1.x);
                fma2(acc[i][3], a2, bb1.y);
            }
        }
        __syncthreads();
    }

    float* dst = (MODE == 0) ? (z == 0 ? g_q : (z == 1 ? g_k : g_v)) : out0;

#pragma unroll
    for (int i = 0; i < 8; i++) {
        const int r = m0 + ((i < 4) ? (ty * 4 + i) : (64 + ty * 4 + (i - 4)));
#pragma unroll
        for (int p = 0; p < 4; p++) {
            const int c = n0 + ((p < 2) ? (tx * 4 + 2 * p)
                                        : (64 + tx * 4 + 2 * (p - 2)));
            float2 v = unpack2(acc[i][p]);
            const float v0 = v.x + bias[c];
            const float v1 = v.y + bias[c + 1];
            if (MODE == 0) {
                const int b = r >> 11;           // / T_SEQ
                const int t = r & (T_SEQ - 1);
                const int h = c >> 6;            // / HDIM
                const int d = c & 63;            // c even -> d,d+1 same head
                float* o = dst + (((size_t)(b * NHEAD + h) * T_SEQ + t) * HDIM);
                o[d]     = v0;
                o[d + 1] = v1;
            } else {
                dst[(size_t)r * C_DIM + c]     = v0;
                dst[(size_t)r * C_DIM + c + 1] = v1;
            }
        }
    }
}

// ---------------- Flash attention (causal, online softmax) -------------------
// grid: (32 query tiles, 64 bh); block: 256 threads
// thread (tx = t&15, ty = t>>4) owns rows r0..r0+3 (r0 = 4*ty) and cols
// c = tx + 16*jj (jj 0..3)  -> conflict-free smem with 65-float row pad.
__global__ __launch_bounds__(256, 2)
void attn_kernel()
{
    extern __shared__ float sm[];
    float* Qs = sm;                 // 64 x 65
    float* Ks = sm + 64 * 65;
    float* Vs = sm + 2 * 64 * 65;
    float* Ps = sm + 3 * 64 * 65;

    const int qtile = (int)gridDim.x - 1 - (int)blockIdx.x;  // heavy blocks first
    const int bh    = blockIdx.y;
    const int tid   = threadIdx.x;
    const int tx    = tid & 15;
    const int ty    = tid >> 4;
    const int r0    = ty * 4;

    const float* qbase = g_q + ((size_t)bh * T_SEQ + qtile * 64) * HDIM;
#pragma unroll
    for (int i = 0; i < 16; ++i) {
        int idx = tid + i * 256;           // 0..4095
        int r = idx >> 6, d = idx & 63;
        Qs[r * 65 + d] = qbase[idx];
    }

    float m[4], l[4], o[4][4];
#pragma unroll
    for (int i = 0; i < 4; ++i) {
        m[i] = -1e30f;
        l[i] = 0.0f;
#pragma unroll
        for (int jj = 0; jj < 4; ++jj) o[i][jj] = 0.0f;
    }
    const float scale = 0.125f;  // 1/sqrt(64)

    for (int j = 0; j <= qtile; ++j) {
        const float* kb = g_k + ((size_t)bh * T_SEQ + j * 64) * HDIM;
        const float* vb = g_v + ((size_t)bh * T_SEQ + j * 64) * HDIM;
        __syncthreads();   // previous tile fully consumed
#pragma unroll
        for (int i = 0; i < 16; ++i) {
            int idx = tid + i * 256;
            int r = idx >> 6, d = idx & 63;
            Ks[r * 65 + d] = kb[idx];
            Vs[r * 65 + d] = vb[idx];
        }
        __syncthreads();

        // S = Q K^T
        float s[4][4];
#pragma unroll
        for (int i = 0; i < 4; ++i)
#pragma unroll
            for (int jj = 0; jj < 4; ++jj) s[i][jj] = 0.0f;

#pragma unroll 8
        for (int d = 0; d < 64; ++d) {
            float qv[4], kv[4];
#pragma unroll
            for (int i = 0; i < 4; ++i)  qv[i]  = Qs[(r0 + i) * 65 + d];
#pragma unroll
            for (int jj = 0; jj < 4; ++jj) kv[jj] = Ks[(tx + 16 * jj) * 65 + d];
#pragma unroll
            for (int i = 0; i < 4; ++i)
#pragma unroll
                for (int jj = 0; jj < 4; ++jj)
                    s[i][jj] = fmaf(qv[i], kv[jj], s[i][jj]);
        }

        const bool diag = (j == qtile);
#pragma unroll
        for (int i = 0; i < 4; ++i)
#pragma unroll
            for (int jj = 0; jj < 4; ++jj) {
                s[i][jj] *= scale;
                if (diag && (tx + 16 * jj) > (r0 + i)) s[i][jj] = -1e30f;
            }

        // row max across the 16 tx-threads
        float mnew[4], alpha[4], ls[4];
#pragma unroll
        for (int i = 0; i < 4; ++i) {
            float v = fmaxf(fmaxf(s[i][0], s[i][1]), fmaxf(s[i][2], s[i][3]));
#pragma unroll
            for (int off = 1; off < 16; off <<= 1)
                v = fmaxf(v, __shfl_xor_sync(0xffffffffu, v, off));
            mnew[i]  = fmaxf(m[i], v);
            alpha[i] = __expf(m[i] - mnew[i]);
        }
#pragma unroll
        for (int i = 0; i < 4; ++i) {
            ls[i] = 0.0f;
#pragma unroll
            for (int jj = 0; jj < 4; ++jj) {
                float p = __expf(s[i][jj] - mnew[i]);
                Ps[(r0 + i) * 65 + tx + 16 * jj] = p;
                ls[i] += p;
            }
        }
#pragma unroll
        for (int i = 0; i < 4; ++i) {
            float v = ls[i];
#pragma unroll
            for (int off = 1; off < 16; off <<= 1)
                v += __shfl_xor_sync(0xffffffffu, v, off);
            l[i] = l[i] * alpha[i] + v;
            m[i] = mnew[i];
#pragma unroll
            for (int jj = 0; jj < 4; ++jj) o[i][jj] *= alpha[i];
        }
        __syncthreads();   // Ps ready

        // O += P V
#pragma unroll 8
        for (int c = 0; c < 64; ++c) {
            float pv[4], vv[4];
#pragma unroll
            for (int i = 0; i < 4; ++i)  pv[i]  = Ps[(r0 + i) * 65 + c];
#pragma unroll
            for (int jj = 0; jj < 4; ++jj) vv[jj] = Vs[c * 65 + tx + 16 * jj];
#pragma unroll
            for (int i = 0; i < 4; ++i)
#pragma unroll
                for (int jj = 0; jj < 4; ++jj)
                    o[i][jj] = fmaf(pv[i], vv[jj], o[i][jj]);
        }
    }

    // epilogue: Y[b, t, h*64 + c] = O / l
    const int b = bh >> 4;
    const int h = bh & 15;
#pragma unroll
    for (int i = 0; i < 4; ++i) {
        const float inv = 1.0f / l[i];
        const int qrow = qtile * 64 + r0 + i;
        float* yb = g_y + ((size_t)(b * T_SEQ + qrow)) * C_DIM + h * HDIM;
#pragma unroll
        for (int jj = 0; jj < 4; ++jj)
            yb[tx + 16 * jj] = o[i][jj] * inv;
    }
}

// ------------------------------------------------------------------------------
extern "C" void kernel_launch(void* const* d_in, const int* in_sizes, int n_in,
                              void* d_out, int out_size)
{
    const float* x  = (const float*)d_in[0];
    const float* Wq = (const float*)d_in[1];
    const float* bq = (const float*)d_in[2];
    const float* Wk = (const float*)d_in[3];
    const float* bk = (const float*)d_in[4];
    const float* Wv = (const float*)d_in[5];
    const float* bv = (const float*)d_in[6];
    const float* Wp = (const float*)d_in[7];
    const float* bp = (const float*)d_in[8];
    float* out = (float*)d_out;

    dim3 blk(256);

    // QKV projections (fused): grid.z = {q,k,v}
    gemm_kernel<0><<<dim3(C_DIM / 128, M_TOT / 128, 3), blk>>>(
        x, Wq, Wk, Wv, bq, bk, bv, nullptr);

    // causal flash attention
    const int smem = 4 * 64 * 65 * (int)sizeof(float);  // 66560 B
    cudaFuncSetAttribute(attn_kernel,
                         cudaFuncAttributeMaxDynamicSharedMemorySize, smem);
    attn_kernel<<<dim3(T_SEQ / 64, BATCH * NHEAD), blk, smem>>>();

    // output projection
    gemm_kernel<1><<<dim3(C_DIM / 128, M_TOT / 128, 1), blk>>>(
        nullptr, Wp, nullptr, nullptr, bp, nullptr, nullptr, out);
}